// round 5
// baseline (speedup 1.0000x reference)
#include <cuda_runtime.h>
#include <math.h>

#define Nn 32
#define Cc 512
#define Pp 1600
#define Kk 64
#define EPSF 1e-12f

#define TP 128     // p-tile for scores kernel
#define CK 32      // c-chunk for scores kernel
#define NPT 13     // ceil(1600/128)
#define PC 32      // p-chunk for agg kernel
#define AST 34     // agg smem stride (PC+2, even for 8B-aligned float2)
#define SSL 130    // scores-smem softmax row stride

// Scratch (no allocations allowed): static device globals
__device__ float g_soft[(size_t)Nn * Kk * Pp];   // 13.1 MB
__device__ float g_agg [(size_t)Nn * Kk * Cc];   // 4 MB
__device__ float g_mass[Nn * Kk];
__device__ float g_gsum[Nn];

// packed fp32x2 helpers (sm_100+ dual-issue fp32 pipe)
#define FMA2(d, a, b, c) \
    asm("fma.rn.f32x2 %0, %1, %2, %3;" : "=l"(d) : "l"(a), "l"(b), "l"(c))
#define PACK_DUP(d, s) \
    asm("mov.b64 %0, {%1, %1};" : "=l"(d) : "f"(s))
#define UNPACK2(lo, hi, s) \
    asm("mov.b64 {%0, %1}, %2;" : "=f"(lo), "=f"(hi) : "l"(s))

// ---------------------------------------------------------------------------
// Kernel 0: zero atomic accumulators (must be reset on every graph replay)
// ---------------------------------------------------------------------------
__global__ void k_zero() {
    int t = blockIdx.x * blockDim.x + threadIdx.x;
    if (t < Nn * Kk) g_mass[t] = 0.f;
    if (t < Nn)      g_gsum[t] = 0.f;
}

// ---------------------------------------------------------------------------
// Kernel 1: scores GEMM (W[64,512] @ X[512,P]) + bias + softmax over k
//           + soft[n,k,p] store + per-block mass partials.
// Block: 128 threads = 8(tk) x 16(tp). Tile 64k x 128p.
// Micro: 8k x 8p, p handled as 4 packed pairs at tp*2 + 32j (+{0,1}).
// FFMA2 inner loop; conflict-free LDS.64 (banks 2*tp).
// ---------------------------------------------------------------------------
__global__ __launch_bounds__(128) void k_scores(const float* __restrict__ x,
                                                const float* __restrict__ conv_w,
                                                const float* __restrict__ conv_b) {
    __shared__ float sbuf[Kk * SSL];    // 8320 floats (33.3 KB); phase A: xs|ws
    __shared__ float sbias[Kk];

    float* xs = sbuf;                   // [CK][TP]     4096 floats
    float* ws = sbuf + CK * TP;         // [Kk][CK+1]   2112 floats

    const int n     = blockIdx.y;
    const int pbase = blockIdx.x * TP;
    const int tid   = threadIdx.x;
    const int tk    = tid >> 4;         // 0..7
    const int tp    = tid & 15;         // 0..15

    if (tid < Kk) sbias[tid] = conv_b[tid];

    unsigned long long acc2[8][4];
#pragma unroll
    for (int i = 0; i < 8; i++)
#pragma unroll
        for (int j = 0; j < 4; j++) acc2[i][j] = 0ull;   // (0.f, 0.f)

    const float* xb = x + (size_t)n * Cc * Pp;

    for (int c0 = 0; c0 < Cc; c0 += CK) {
        __syncthreads();
        // x chunk [CK][TP] via float4 (coalesced, zero-fill OOB p)
        for (int i = tid; i < CK * TP / 4; i += 128) {
            int c  = i >> 5;            // 32 float4 per row
            int p4 = i & 31;
            int p  = pbase + p4 * 4;
            float4 v = make_float4(0.f, 0.f, 0.f, 0.f);
            if (p < Pp) v = *(const float4*)(xb + (size_t)(c0 + c) * Pp + p);
            *(float4*)(xs + c * TP + p4 * 4) = v;
        }
        // w chunk [Kk][CK] padded rows
        for (int i = tid; i < Kk * CK; i += 128) {
            int k = i >> 5, c = i & 31;
            ws[k * (CK + 1) + c] = conv_w[k * Cc + c0 + c];
        }
        __syncthreads();

#pragma unroll 4
        for (int c = 0; c < CK; c++) {
            unsigned long long xv[4];
#pragma unroll
            for (int j = 0; j < 4; j++)
                xv[j] = *(const unsigned long long*)(xs + c * TP + tp * 2 + 32 * j);
#pragma unroll
            for (int i = 0; i < 8; i++) {
                float w = ws[(tk * 8 + i) * (CK + 1) + c];
                unsigned long long w2;
                PACK_DUP(w2, w);
#pragma unroll
                for (int j = 0; j < 4; j++)
                    FMA2(acc2[i][j], w2, xv[j], acc2[i][j]);
            }
        }
    }
    __syncthreads();

    // dump scores tile into smem ss[64][SSL] as packed pairs (STS.64)
#pragma unroll
    for (int i = 0; i < 8; i++)
#pragma unroll
        for (int j = 0; j < 4; j++)
            *(unsigned long long*)(sbuf + (tk * 8 + i) * SSL + tp * 2 + 32 * j) = acc2[i][j];
    __syncthreads();

    // softmax over k: one p-column per thread
    {
        const int p = pbase + tid;
        if (p < Pp) {
            float mx = -3.4e38f;
            for (int k = 0; k < Kk; k++) {
                float v = sbuf[k * SSL + tid] + sbias[k];
                sbuf[k * SSL + tid] = v;
                mx = fmaxf(mx, v);
            }
            float sum = 0.f;
            for (int k = 0; k < Kk; k++) {
                float e = __expf(sbuf[k * SSL + tid] - mx);
                sbuf[k * SSL + tid] = e;
                sum += e;
            }
            float inv = 1.f / sum;
            for (int k = 0; k < Kk; k++) {
                float sv = sbuf[k * SSL + tid] * inv;
                sbuf[k * SSL + tid] = sv;
                g_soft[((size_t)n * Kk + k) * Pp + p] = sv;
            }
        } else {
            for (int k = 0; k < Kk; k++) sbuf[k * SSL + tid] = 0.f;
        }
    }
    __syncthreads();

    // mass[n,k] partial: row sums of soft tile
    if (tid < Kk) {
        float s = 0.f;
        for (int j = 0; j < TP; j++) s += sbuf[tid * SSL + j];
        atomicAdd(&g_mass[n * Kk + tid], s);
    }
}

// ---------------------------------------------------------------------------
// Kernel 2: agg[n,k,c] = sum_p soft[n,k,p] * x[n,c,p]  (A @ B^T per n)
// Block: 256 threads = 16(tk) x 16(tc). Tile 64k x 128c.
// Micro: 4k x 8c (c = tc + 16j -> conflict-free banks 2*tc).
// Reduction packed: pairs (2q, 2q+1) over p, horizontal add at the end.
// ---------------------------------------------------------------------------
__global__ __launch_bounds__(256) void k_agg(const float* __restrict__ x) {
    __shared__ float as_[Kk * AST];     // soft chunk [64k][32p] stride 34
    __shared__ float bs_[128 * AST];    // x    chunk [128c][32p] stride 34

    const int n   = blockIdx.y;
    const int c0  = blockIdx.x * 128;
    const int tid = threadIdx.x;
    const int tk  = tid >> 4;
    const int tc  = tid & 15;

    unsigned long long acc2[4][8];
#pragma unroll
    for (int i = 0; i < 4; i++)
#pragma unroll
        for (int j = 0; j < 8; j++) acc2[i][j] = 0ull;

    const float* softb = g_soft + (size_t)n * Kk * Pp;
    const float* xb    = x + (size_t)n * Cc * Pp + (size_t)c0 * Pp;

    for (int p0 = 0; p0 < Pp; p0 += PC) {   // 50 chunks, exact
        __syncthreads();
        for (int i = tid; i < Kk * PC; i += 256) {
            int k = i >> 5, pi = i & 31;
            as_[k * AST + pi] = softb[(size_t)k * Pp + p0 + pi];
        }
        for (int i = tid; i < 128 * PC; i += 256) {
            int ci = i >> 5, pi = i & 31;
            bs_[ci * AST + pi] = xb[(size_t)ci * Pp + p0 + pi];
        }
        __syncthreads();

#pragma unroll 8
        for (int q = 0; q < PC / 2; q++) {
            unsigned long long a2[4], b2[8];
#pragma unroll
            for (int i = 0; i < 4; i++)
                a2[i] = *(const unsigned long long*)(as_ + (tk * 4 + i) * AST + 2 * q);
#pragma unroll
            for (int j = 0; j < 8; j++)
                b2[j] = *(const unsigned long long*)(bs_ + (tc + 16 * j) * AST + 2 * q);
#pragma unroll
            for (int i = 0; i < 4; i++)
#pragma unroll
                for (int j = 0; j < 8; j++)
                    FMA2(acc2[i][j], a2[i], b2[j], acc2[i][j]);
        }
    }

    // horizontal add of pair halves + store (coalesced over tc)
#pragma unroll
    for (int i = 0; i < 4; i++) {
        float* dst = &g_agg[((size_t)n * Kk + tk * 4 + i) * Cc + c0];
#pragma unroll
        for (int j = 0; j < 8; j++) {
            float lo, hi;
            UNPACK2(lo, hi, acc2[i][j]);
            dst[tc + 16 * j] = lo + hi;
        }
    }
}

// ---------------------------------------------------------------------------
// Kernel 3: vlad = agg - mass*centroid; intra-L2-norm per (n,k) row;
//           accumulate per-n global sumsq.
// ---------------------------------------------------------------------------
__global__ __launch_bounds__(128) void k_vlad(const float* __restrict__ centroids,
                                              float* __restrict__ out) {
    const int n   = blockIdx.x >> 6;
    const int k   = blockIdx.x & 63;
    const int tid = threadIdx.x;

    const float m = g_mass[n * Kk + k];
    const int c = tid * 4;

    float4 a  = *(const float4*)&g_agg[((size_t)n * Kk + k) * Cc + c];
    float4 ce = *(const float4*)&centroids[k * Cc + c];
    float4 v;
    v.x = a.x - m * ce.x;
    v.y = a.y - m * ce.y;
    v.z = a.z - m * ce.z;
    v.w = a.w - m * ce.w;

    float ssq = v.x * v.x + v.y * v.y + v.z * v.z + v.w * v.w;
#pragma unroll
    for (int off = 16; off > 0; off >>= 1)
        ssq += __shfl_xor_sync(0xffffffffu, ssq, off);

    __shared__ float red[4];
    const int warp = tid >> 5, lane = tid & 31;
    if (lane == 0) red[warp] = ssq;
    __syncthreads();
    const float tot = red[0] + red[1] + red[2] + red[3];

    const float t   = fmaxf(sqrtf(tot), EPSF);
    const float inv = 1.f / t;

    float4 o;
    o.x = v.x * inv; o.y = v.y * inv; o.z = v.z * inv; o.w = v.w * inv;
    *(float4*)&out[(size_t)n * (Kk * Cc) + k * Cc + c] = o;

    if (tid == 0) atomicAdd(&g_gsum[n], tot * inv * inv);
}

// ---------------------------------------------------------------------------
// Kernel 4: global L2 rescale per n
// ---------------------------------------------------------------------------
__global__ __launch_bounds__(256) void k_gnorm(float* __restrict__ out) {
    const int n = blockIdx.y;
    const float scale = 1.f / fmaxf(sqrtf(g_gsum[n]), EPSF);
    const int idx = blockIdx.x * blockDim.x + threadIdx.x;   // float4 index
    float4* o = (float4*)(out + (size_t)n * Kk * Cc);
    float4 v = o[idx];
    v.x *= scale; v.y *= scale; v.z *= scale; v.w *= scale;
    o[idx] = v;
}

// ---------------------------------------------------------------------------
extern "C" void kernel_launch(void* const* d_in, const int* in_sizes, int n_in,
                              void* d_out, int out_size) {
    const float* x         = (const float*)d_in[0];  // [32,512,40,40]
    const float* centroids = (const float*)d_in[1];  // [64,512]
    const float* conv_w    = (const float*)d_in[2];  // [64,512]
    const float* conv_b    = (const float*)d_in[3];  // [64]
    float* out = (float*)d_out;                      // [32, 64*512]

    k_zero<<<(Nn * Kk + 255) / 256, 256>>>();

    dim3 g1(NPT, Nn);
    k_scores<<<g1, 128>>>(x, conv_w, conv_b);

    dim3 g2(Cc / 128, Nn);
    k_agg<<<g2, 256>>>(x);

    k_vlad<<<Nn * Kk, 128>>>(centroids, out);

    dim3 g4(Kk * Cc / 4 / 256, Nn);   // 32 x 32
    k_gnorm<<<g4, 256>>>(out);
}

// round 7
// speedup vs baseline: 1.0874x; 1.0874x over previous
#include <cuda_runtime.h>
#include <math.h>

#define Nn 32
#define Cc 512
#define Pp 1600
#define Kk 64
#define EPSF 1e-12f

#define TP 128     // p-tile for scores kernel
#define CK 32      // c-chunk for scores kernel
#define CHN 16     // Cc/CK
#define NPT 13     // ceil(1600/128)
#define PC 32      // p-chunk for agg kernel
#define SSL 130    // scores-smem softmax row stride

// Scratch (no allocations allowed): static device globals
__device__ float g_soft[(size_t)Nn * Kk * Pp];   // 13.1 MB
__device__ float g_agg [(size_t)Nn * Kk * Cc];   // 4 MB
__device__ float g_mass[Nn * Kk];
__device__ float g_gsum[Nn];

// ---------------------------------------------------------------------------
// Kernel 0: zero atomic accumulators (reset on every graph replay)
// ---------------------------------------------------------------------------
__global__ void k_zero() {
    int t = blockIdx.x * blockDim.x + threadIdx.x;
    if (t < Nn * Kk) g_mass[t] = 0.f;
    if (t < Nn)      g_gsum[t] = 0.f;
}

// ---------------------------------------------------------------------------
// Kernel 1: scores GEMM (W[64,512] @ X[512,P]) + bias + softmax over k
//           + soft store + per-block mass partials.  DOUBLE BUFFERED.
// Block 256 = 16(tk) x 16(tp). Tile 64k x 128p, micro 4k x 8p.
// smem: xs[2][32][128] + ws[2][64][32] = 12288 floats = 48KB (softmax aliases).
// ---------------------------------------------------------------------------
__global__ __launch_bounds__(256) void k_scores(const float* __restrict__ x,
                                                const float* __restrict__ conv_w,
                                                const float* __restrict__ conv_b) {
    __shared__ float smem[12288];

    const int n     = blockIdx.y;
    const int pbase = blockIdx.x * TP;
    const int tid   = threadIdx.x;
    const int tk    = tid >> 4;     // 0..15
    const int tp    = tid & 15;     // 0..15

    float bias[4];
#pragma unroll
    for (int i = 0; i < 4; i++) bias[i] = conv_b[tk * 4 + i];

    float acc[4][8];
#pragma unroll
    for (int i = 0; i < 4; i++)
#pragma unroll
        for (int j = 0; j < 8; j++) acc[i][j] = 0.f;

    const float* xb = x + (size_t)n * Cc * Pp;

    float4 xr[4], wr[2];

#define SC_LDG(c0)                                                              \
    {                                                                           \
        _Pragma("unroll")                                                       \
        for (int r = 0; r < 4; r++) {                                           \
            int f = tid + 256 * r;                                              \
            int c = f >> 5, p4 = f & 31;                                        \
            int p = pbase + p4 * 4;                                             \
            xr[r] = (p < Pp) ? *(const float4*)(xb + (size_t)((c0) + c) * Pp + p) \
                             : make_float4(0.f, 0.f, 0.f, 0.f);                 \
        }                                                                       \
        _Pragma("unroll")                                                       \
        for (int r = 0; r < 2; r++) {                                           \
            int f = tid + 256 * r;                                              \
            int k = f >> 3, c4 = f & 7;                                         \
            wr[r] = *(const float4*)(conv_w + k * Cc + (c0) + c4 * 4);          \
        }                                                                       \
    }

#define SC_STS(buf)                                                             \
    {                                                                           \
        float* xs_ = smem + (buf) * 4096;                                       \
        float* ws_ = smem + 8192 + (buf) * 2048;                                \
        _Pragma("unroll")                                                       \
        for (int r = 0; r < 4; r++) {                                           \
            int f = tid + 256 * r;                                              \
            int c = f >> 5, p4 = f & 31;                                        \
            *(float4*)(xs_ + c * TP + p4 * 4) = xr[r];                          \
        }                                                                       \
        _Pragma("unroll")                                                       \
        for (int r = 0; r < 2; r++) {                                           \
            int f = tid + 256 * r;                                              \
            int k = f >> 3, c4 = f & 7;                                         \
            *(float4*)(ws_ + k * CK + c4 * 4) = wr[r];                          \
        }                                                                       \
    }

    SC_LDG(0);
    SC_STS(0);
    int cur = 0;

    for (int ch = 0; ch < CHN; ch++) {
        __syncthreads();
        if (ch + 1 < CHN) SC_LDG((ch + 1) * CK);

        const float* xs_ = smem + cur * 4096;
        const float* ws_ = smem + 8192 + cur * 2048;
#pragma unroll 4
        for (int c = 0; c < CK; c++) {
            float4 xv0 = *(const float4*)(xs_ + c * TP + tp * 8);
            float4 xv1 = *(const float4*)(xs_ + c * TP + tp * 8 + 4);
            float xv[8] = {xv0.x, xv0.y, xv0.z, xv0.w, xv1.x, xv1.y, xv1.z, xv1.w};
#pragma unroll
            for (int i = 0; i < 4; i++) {
                float wv = ws_[(tk * 4 + i) * CK + c];
#pragma unroll
                for (int j = 0; j < 8; j++)
                    acc[i][j] = fmaf(wv, xv[j], acc[i][j]);
            }
        }
        if (ch + 1 < CHN) SC_STS(cur ^ 1);
        cur ^= 1;
    }
    __syncthreads();

    // dump scores (+bias) into smem ss[64][SSL]
    float* ss = smem;
#pragma unroll
    for (int i = 0; i < 4; i++)
#pragma unroll
        for (int j = 0; j < 8; j++)
            ss[(tk * 4 + i) * SSL + tp * 8 + j] = acc[i][j] + bias[i];
    __syncthreads();

    // softmax over k: one p-column per thread (threads 0..127)
    if (tid < TP) {
        const int p = pbase + tid;
        if (p < Pp) {
            float mx = -3.4e38f;
            for (int k = 0; k < Kk; k++) mx = fmaxf(mx, ss[k * SSL + tid]);
            float sum = 0.f;
            for (int k = 0; k < Kk; k++) {
                float e = __expf(ss[k * SSL + tid] - mx);
                ss[k * SSL + tid] = e;
                sum += e;
            }
            float inv = 1.f / sum;
            for (int k = 0; k < Kk; k++) {
                float sv = ss[k * SSL + tid] * inv;
                ss[k * SSL + tid] = sv;
                g_soft[((size_t)n * Kk + k) * Pp + p] = sv;
            }
        } else {
            for (int k = 0; k < Kk; k++) ss[k * SSL + tid] = 0.f;
        }
    }
    __syncthreads();

    // mass[n,k] partials
    if (tid < Kk) {
        float s = 0.f;
        for (int j = 0; j < TP; j++) s += ss[tid * SSL + j];
        atomicAdd(&g_mass[n * Kk + tid], s);
    }
#undef SC_LDG
#undef SC_STS
}

// ---------------------------------------------------------------------------
// Kernel 2: agg[n,k,c] = sum_p soft[n,k,p] * x[n,c,p].  DOUBLE BUFFERED.
// Block 256 = 16(tk) x 16(tc). Tile 64k x 64c, micro 4k x 4c.
// smem: as[2][64][32] + bs[2][32][64] (x transposed -> conflict-free) = 32KB.
// ---------------------------------------------------------------------------
__global__ __launch_bounds__(256) void k_agg(const float* __restrict__ x) {
    __shared__ float smem[8192];

    const int n   = blockIdx.y;
    const int c0  = blockIdx.x * 64;
    const int tid = threadIdx.x;
    const int tk  = tid >> 4;
    const int tc  = tid & 15;

    float acc[4][4];
#pragma unroll
    for (int i = 0; i < 4; i++)
#pragma unroll
        for (int j = 0; j < 4; j++) acc[i][j] = 0.f;

    const float* sb = g_soft + (size_t)n * Kk * Pp;
    const float* xb = x + (size_t)n * Cc * Pp + (size_t)c0 * Pp;

    float4 ar[2], br[2];

#define AG_LDG(p0)                                                              \
    {                                                                           \
        _Pragma("unroll")                                                       \
        for (int r = 0; r < 2; r++) {                                           \
            int f = tid + 256 * r;                                              \
            int k = f >> 3, p4 = f & 7;                                         \
            ar[r] = *(const float4*)(sb + (size_t)k * Pp + (p0) + p4 * 4);      \
        }                                                                       \
        _Pragma("unroll")                                                       \
        for (int r = 0; r < 2; r++) {                                           \
            int f = tid + 256 * r;                                              \
            int ci = f >> 3, p4 = f & 7;                                        \
            br[r] = *(const float4*)(xb + (size_t)ci * Pp + (p0) + p4 * 4);     \
        }                                                                       \
    }

#define AG_STS(buf)                                                             \
    {                                                                           \
        float* as_ = smem + (buf) * 2048;                                       \
        float* bs_ = smem + 4096 + (buf) * 2048;                                \
        _Pragma("unroll")                                                       \
        for (int r = 0; r < 2; r++) {                                           \
            int f = tid + 256 * r;                                              \
            int k = f >> 3, p4 = f & 7;                                         \
            *(float4*)(as_ + k * PC + p4 * 4) = ar[r];                          \
        }                                                                       \
        _Pragma("unroll")                                                       \
        for (int r = 0; r < 2; r++) {                                           \
            int f = tid + 256 * r;                                              \
            int ci = f >> 3, p4 = f & 7;                                        \
            bs_[(p4 * 4 + 0) * 64 + ci] = br[r].x;                              \
            bs_[(p4 * 4 + 1) * 64 + ci] = br[r].y;                              \
            bs_[(p4 * 4 + 2) * 64 + ci] = br[r].z;                              \
            bs_[(p4 * 4 + 3) * 64 + ci] = br[r].w;                              \
        }                                                                       \
    }

    AG_LDG(0);
    AG_STS(0);
    int cur = 0;

    for (int ch = 0; ch < Pp / PC; ch++) {   // 50 chunks, exact
        __syncthreads();
        if (ch + 1 < Pp / PC) AG_LDG((ch + 1) * PC);

        const float* as_ = smem + cur * 2048;
        const float* bs_ = smem + 4096 + cur * 2048;
#pragma unroll 8
        for (int pi = 0; pi < PC; pi++) {
            float a[4], b[4];
#pragma unroll
            for (int i = 0; i < 4; i++) a[i] = as_[(tk * 4 + i) * PC + pi];
#pragma unroll
            for (int j = 0; j < 4; j++) b[j] = bs_[pi * 64 + tc + 16 * j];
#pragma unroll
            for (int i = 0; i < 4; i++)
#pragma unroll
                for (int j = 0; j < 4; j++)
                    acc[i][j] = fmaf(a[i], b[j], acc[i][j]);
        }
        if (ch + 1 < Pp / PC) AG_STS(cur ^ 1);
        cur ^= 1;
    }

#pragma unroll
    for (int i = 0; i < 4; i++) {
        float* dst = &g_agg[((size_t)n * Kk + tk * 4 + i) * Cc + c0];
#pragma unroll
        for (int j = 0; j < 4; j++)
            dst[tc + 16 * j] = acc[i][j];
    }
#undef AG_LDG
#undef AG_STS
}

// ---------------------------------------------------------------------------
// Kernel 3: vlad = agg - mass*centroid; intra-L2-norm per (n,k) row;
//           accumulate per-n global sumsq.
// ---------------------------------------------------------------------------
__global__ __launch_bounds__(128) void k_vlad(const float* __restrict__ centroids,
                                              float* __restrict__ out) {
    const int n   = blockIdx.x >> 6;
    const int k   = blockIdx.x & 63;
    const int tid = threadIdx.x;

    const float m = g_mass[n * Kk + k];
    const int c = tid * 4;

    float4 a  = *(const float4*)&g_agg[((size_t)n * Kk + k) * Cc + c];
    float4 ce = *(const float4*)&centroids[k * Cc + c];
    float4 v;
    v.x = a.x - m * ce.x;
    v.y = a.y - m * ce.y;
    v.z = a.z - m * ce.z;
    v.w = a.w - m * ce.w;

    float ssq = v.x * v.x + v.y * v.y + v.z * v.z + v.w * v.w;
#pragma unroll
    for (int off = 16; off > 0; off >>= 1)
        ssq += __shfl_xor_sync(0xffffffffu, ssq, off);

    __shared__ float red[4];
    const int warp = tid >> 5, lane = tid & 31;
    if (lane == 0) red[warp] = ssq;
    __syncthreads();
    const float tot = red[0] + red[1] + red[2] + red[3];

    const float t   = fmaxf(sqrtf(tot), EPSF);
    const float inv = 1.f / t;

    float4 o;
    o.x = v.x * inv; o.y = v.y * inv; o.z = v.z * inv; o.w = v.w * inv;
    *(float4*)&out[(size_t)n * (Kk * Cc) + k * Cc + c] = o;

    if (tid == 0) atomicAdd(&g_gsum[n], tot * inv * inv);
}

// ---------------------------------------------------------------------------
// Kernel 4: global L2 rescale per n
// ---------------------------------------------------------------------------
__global__ __launch_bounds__(256) void k_gnorm(float* __restrict__ out) {
    const int n = blockIdx.y;
    const float scale = 1.f / fmaxf(sqrtf(g_gsum[n]), EPSF);
    const int idx = blockIdx.x * blockDim.x + threadIdx.x;   // float4 index
    float4* o = (float4*)(out + (size_t)n * Kk * Cc);
    float4 v = o[idx];
    v.x *= scale; v.y *= scale; v.z *= scale; v.w *= scale;
    o[idx] = v;
}

// ---------------------------------------------------------------------------
extern "C" void kernel_launch(void* const* d_in, const int* in_sizes, int n_in,
                              void* d_out, int out_size) {
    const float* x         = (const float*)d_in[0];  // [32,512,40,40]
    const float* centroids = (const float*)d_in[1];  // [64,512]
    const float* conv_w    = (const float*)d_in[2];  // [64,512]
    const float* conv_b    = (const float*)d_in[3];  // [64]
    float* out = (float*)d_out;                      // [32, 64*512]

    k_zero<<<(Nn * Kk + 255) / 256, 256>>>();

    dim3 g1(NPT, Nn);
    k_scores<<<g1, 256>>>(x, conv_w, conv_b);

    dim3 g2(Cc / 64, Nn);
    k_agg<<<g2, 256>>>(x);

    k_vlad<<<Nn * Kk, 128>>>(centroids, out);

    dim3 g4(Kk * Cc / 4 / 256, Nn);   // 32 x 32
    k_gnorm<<<g4, 256>>>(out);
}